// round 1
// baseline (speedup 1.0000x reference)
#include <cuda_runtime.h>

// Problem constants
#define TOTAL_DIM 24976   // 1*400 + 60*256 + 36*256
#define D_MODEL   512
#define NQ        97
#define BM        32
#define BK        16
#define THREADS   128

typedef unsigned long long u64t;

__device__ __forceinline__ u64t splat2(float x) {
    u64t r; asm("mov.b64 %0, {%1, %1};" : "=l"(r) : "f"(x)); return r;
}
__device__ __forceinline__ void fma2(u64t& d, u64t a, u64t b) {
    asm("fma.rn.f32x2 %0, %1, %2, %0;" : "+l"(d) : "l"(a), "l"(b));
}
__device__ __forceinline__ float2 unpack2(u64t v) {
    float2 f; asm("mov.b64 {%0, %1}, %2;" : "=f"(f.x), "=f"(f.y) : "l"(v)); return f;
}

// One block: 32 output rows x full 512 cols.  GEMM (K=L) + bias + ReLU + LayerNorm.
// 128 threads = 4 warps. Warp w owns rows [w*8, w*8+8); lane owns cols {lane*4 + g*128}.
__global__ __launch_bounds__(THREADS, 2)
void fc_relu_ln_kernel(const float* __restrict__ x,
                       const float* __restrict__ W,     // [L][512]
                       const float* __restrict__ bias,  // [512]
                       const float* __restrict__ gamma, // [512]
                       const float* __restrict__ beta,  // [512]
                       float* __restrict__ out,         // [2048][97][512]
                       int L, int Ksplit, int seg_off, int q_off)
{
    __shared__ float As[BK][BM];        // A tile, transposed: As[k][row]
    __shared__ float Bs[BK][D_MODEL];   // B tile: Bs[k][col]

    const int tid  = threadIdx.x;
    const int lane = tid & 31;
    const int wid  = tid >> 5;              // warp id: rows wid*8 .. wid*8+7
    const int row0 = blockIdx.x * BM;       // first global row of this tile

    // 8 rows x 4 col-groups x 2 packed-pairs of f32x2 accumulators (= 8x16 floats)
    u64t acc[8][4][2];
#pragma unroll
    for (int r = 0; r < 8; r++)
#pragma unroll
        for (int g = 0; g < 4; g++) { acc[r][g][0] = 0ULL; acc[r][g][1] = 0ULL; }

    // A-load mapping: 4 threads per row, each loads one float4 of the 16-wide k-slab
    const int a_row = tid >> 2;   // 0..31
    const int a_kg  = tid & 3;    // k-group 0..3
    const float* xrow;
    {
        int gr = row0 + a_row;
        int bb = gr / Ksplit;
        int jj = gr - bb * Ksplit;
        xrow = x + (size_t)bb * TOTAL_DIM + seg_off + (size_t)jj * L;
    }

    for (int kk = 0; kk < L; kk += BK) {
        // ---- load A tile (32 x 16) transposed into smem ----
        float4 av = *(const float4*)(xrow + kk + a_kg * 4);
        As[a_kg * 4 + 0][a_row] = av.x;
        As[a_kg * 4 + 1][a_row] = av.y;
        As[a_kg * 4 + 2][a_row] = av.z;
        As[a_kg * 4 + 3][a_row] = av.w;

        // ---- load B tile (16 x 512) : 2048 float4, 16 per thread, coalesced ----
#pragma unroll
        for (int i = 0; i < 16; i++) {
            int fi = tid + i * THREADS;      // 0..2047 (float4 index)
            int kr = fi >> 7;                // 512/4 = 128 float4 per row
            int c4 = fi & 127;
            *(float4*)&Bs[kr][c4 * 4] =
                *(const float4*)(W + (size_t)(kk + kr) * D_MODEL + c4 * 4);
        }
        __syncthreads();

        // ---- MMA: packed f32x2 FFMA ----
#pragma unroll
        for (int k = 0; k < BK; k++) {
            float4 a0 = *(const float4*)&As[k][wid * 8];       // warp-broadcast
            float4 a1 = *(const float4*)&As[k][wid * 8 + 4];
            u64t as_[8];
            as_[0] = splat2(a0.x); as_[1] = splat2(a0.y);
            as_[2] = splat2(a0.z); as_[3] = splat2(a0.w);
            as_[4] = splat2(a1.x); as_[5] = splat2(a1.y);
            as_[6] = splat2(a1.z); as_[7] = splat2(a1.w);
#pragma unroll
            for (int g = 0; g < 4; g++) {
                // lane-contiguous float4 -> conflict-free LDS.128
                ulonglong2 bv = *(const ulonglong2*)&Bs[k][lane * 4 + g * 128];
#pragma unroll
                for (int r = 0; r < 8; r++) {
                    fma2(acc[r][g][0], as_[r], bv.x);
                    fma2(acc[r][g][1], as_[r], bv.y);
                }
            }
        }
        __syncthreads();
    }

    // ================= epilogue: bias + ReLU + LayerNorm =================
    float4 bi[4];
#pragma unroll
    for (int g = 0; g < 4; g++)
        bi[g] = *(const float4*)(bias + g * 128 + lane * 4);

    float v[8][4][4];
    float sum[8], ssq[8];
#pragma unroll
    for (int r = 0; r < 8; r++) { sum[r] = 0.f; ssq[r] = 0.f; }

#pragma unroll
    for (int r = 0; r < 8; r++) {
#pragma unroll
        for (int g = 0; g < 4; g++) {
            float2 p0 = unpack2(acc[r][g][0]);
            float2 p1 = unpack2(acc[r][g][1]);
            float h0 = fmaxf(p0.x + bi[g].x, 0.f);
            float h1 = fmaxf(p0.y + bi[g].y, 0.f);
            float h2 = fmaxf(p1.x + bi[g].z, 0.f);
            float h3 = fmaxf(p1.y + bi[g].w, 0.f);
            v[r][g][0] = h0; v[r][g][1] = h1; v[r][g][2] = h2; v[r][g][3] = h3;
            sum[r] += (h0 + h1) + (h2 + h3);
            ssq[r] += (h0 * h0 + h1 * h1) + (h2 * h2 + h3 * h3);
        }
    }

    // warp-wide reduction over the 32 lanes (each row lives entirely in one warp)
#pragma unroll
    for (int r = 0; r < 8; r++) {
#pragma unroll
        for (int o = 16; o > 0; o >>= 1) {
            sum[r] += __shfl_xor_sync(0xffffffffu, sum[r], o);
            ssq[r] += __shfl_xor_sync(0xffffffffu, ssq[r], o);
        }
    }

    float4 gm[4], bt[4];
#pragma unroll
    for (int g = 0; g < 4; g++) {
        gm[g] = *(const float4*)(gamma + g * 128 + lane * 4);
        bt[g] = *(const float4*)(beta  + g * 128 + lane * 4);
    }

    const float invD = 1.0f / (float)D_MODEL;
#pragma unroll
    for (int r = 0; r < 8; r++) {
        float mean = sum[r] * invD;
        float var  = ssq[r] * invD - mean * mean;   // population var (jnp.var)
        float sc   = rsqrtf(var + 1e-5f);

        int gr = row0 + wid * 8 + r;
        int bb = gr / Ksplit;
        int jj = gr - bb * Ksplit;
        float* orow = out + ((size_t)bb * NQ + q_off + jj) * D_MODEL;
#pragma unroll
        for (int g = 0; g < 4; g++) {
            float4 o;
            o.x = (v[r][g][0] - mean) * sc * gm[g].x + bt[g].x;
            o.y = (v[r][g][1] - mean) * sc * gm[g].y + bt[g].y;
            o.z = (v[r][g][2] - mean) * sc * gm[g].z + bt[g].z;
            o.w = (v[r][g][3] - mean) * sc * gm[g].w + bt[g].w;
            *(float4*)(orow + g * 128 + lane * 4) = o;
        }
    }
}

extern "C" void kernel_launch(void* const* d_in, const int* in_sizes, int n_in,
                              void* d_out, int out_size) {
    (void)in_sizes; (void)n_in; (void)out_size;
    const float* x = (const float*)d_in[0];
    float* out = (float*)d_out;

    // split 0: K=1,  L=400, seg_off=0,     q_off=0,  rows=2048
    fc_relu_ln_kernel<<<2048 / BM, THREADS>>>(
        x, (const float*)d_in[1], (const float*)d_in[2],
        (const float*)d_in[3], (const float*)d_in[4], out, 400, 1, 0, 0);

    // split 1: K=60, L=256, seg_off=400,   q_off=1,  rows=122880
    fc_relu_ln_kernel<<<(2048 * 60) / BM, THREADS>>>(
        x, (const float*)d_in[5], (const float*)d_in[6],
        (const float*)d_in[7], (const float*)d_in[8], out, 256, 60, 400, 1);

    // split 2: K=36, L=256, seg_off=15760, q_off=61, rows=73728
    fc_relu_ln_kernel<<<(2048 * 36) / BM, THREADS>>>(
        x, (const float*)d_in[9], (const float*)d_in[10],
        (const float*)d_in[11], (const float*)d_in[12], out, 256, 36, 15760, 61);
}

// round 3
// speedup vs baseline: 2.0959x; 2.0959x over previous
#include <cuda_runtime.h>
#include <cuda_bf16.h>
#include <cstdint>

#define TOTAL_DIM 24976
#define NQ        97
#define THREADS   512

// ---- dynamic SMEM layout (bytes) ----
#define OFF_BIAS  0
#define OFF_GAMMA 2048
#define OFF_BETA  4096
#define OFF_SSUM  6144     // [64][8] f32
#define OFF_SSSQ  8192     // [64][8] f32
#define OFF_RST   10240    // [64][2] f32
#define OFF_A     10752    // 2 stages x 2 planes x 64 rows x 40 halfs (80B row)
#define A_STAGE   10240
#define A_PLANE   5120
#define A_ROWB    80
#define OFF_B     31232    // 2 stages x 2 planes x 32 rows x 520 halfs (1040B row)
#define B_STAGE   66560
#define B_PLANE   33280
#define B_ROWB    1040
#define SMEM_TOTAL 164352

// ---- prepped weights: bf16 hi/lo planes, [Kpad][512], 16B-aligned ----
__device__ uint4 g_bh0[416 * 512 * 2 / 16], g_bl0[416 * 512 * 2 / 16];
__device__ uint4 g_bh1[256 * 512 * 2 / 16], g_bl1[256 * 512 * 2 / 16];
__device__ uint4 g_bh2[256 * 512 * 2 / 16], g_bl2[256 * 512 * 2 / 16];

__device__ __forceinline__ uint32_t smem_u32(const void* p) {
    uint32_t a;
    asm("{ .reg .u64 t; cvta.to.shared.u64 t, %1; cvt.u32.u64 %0, t; }" : "=r"(a) : "l"(p));
    return a;
}
#define LDSM_X4(r0, r1, r2, r3, a) \
    asm volatile("ldmatrix.sync.aligned.m8n8.x4.shared.b16 {%0,%1,%2,%3}, [%4];" \
                 : "=r"(r0), "=r"(r1), "=r"(r2), "=r"(r3) : "r"(a))
#define LDSM_X4T(r0, r1, r2, r3, a) \
    asm volatile("ldmatrix.sync.aligned.m8n8.x4.trans.shared.b16 {%0,%1,%2,%3}, [%4];" \
                 : "=r"(r0), "=r"(r1), "=r"(r2), "=r"(r3) : "r"(a))
#define MMA16816(c, a0, a1, a2, a3, b0, b1) \
    asm volatile("mma.sync.aligned.m16n8k16.row.col.f32.bf16.bf16.f32 " \
                 "{%0,%1,%2,%3}, {%4,%5,%6,%7}, {%8,%9}, {%0,%1,%2,%3};" \
                 : "+f"((c)[0]), "+f"((c)[1]), "+f"((c)[2]), "+f"((c)[3]) \
                 : "r"(a0), "r"(a1), "r"(a2), "r"(a3), "r"(b0), "r"(b1))
__device__ __forceinline__ void cp16(uint32_t dst, const void* src) {
    asm volatile("cp.async.cg.shared.global [%0], [%1], 16;" :: "r"(dst), "l"(src));
}
__device__ __forceinline__ void bf16_split(float v, uint16_t& h, uint16_t& l) {
    __nv_bfloat16 hb = __float2bfloat16_rn(v);
    __nv_bfloat16 lb = __float2bfloat16_rn(v - __bfloat162float(hb));
    h = *(uint16_t*)&hb; l = *(uint16_t*)&lb;
}

// ================= fused GEMM + bias + ReLU + LayerNorm =================
template <int KSPLIT, int LVALID, int NCHUNK, int SEGOFF, int QOFF>
__device__ __forceinline__ void run_split(const float* __restrict__ x,
                                          const float* __restrict__ bias_g,
                                          const float* __restrict__ gamma_g,
                                          const float* __restrict__ beta_g,
                                          float* __restrict__ out,
                                          const uint4* __restrict__ wbh,
                                          const uint4* __restrict__ wbl,
                                          int tile) {
    extern __shared__ char smem[];
    const uint32_t sb = smem_u32(smem);
    const int tid = threadIdx.x, lane = tid & 31, wid = tid >> 5;
    const int wm = wid & 1;        // row group: rows wm*32..+32
    const int wn = wid >> 1;       // col group: cols wn*64..+64
    const int row0 = tile * 64;

    float* bias_s = (float*)(smem + OFF_BIAS);
    float* gam_s  = (float*)(smem + OFF_GAMMA);
    float* bet_s  = (float*)(smem + OFF_BETA);
    for (int i = tid; i < 512; i += THREADS) {
        bias_s[i] = bias_g[i]; gam_s[i] = gamma_g[i]; bet_s[i] = beta_g[i];
    }

    // per-thread x mapping: one row, one float4 column slot
    const int xrow = tid >> 3, xf4 = tid & 7;
    const float* px;
    {
        int gr = row0 + xrow;
        int bb = gr / KSPLIT, jj = gr - bb * KSPLIT;
        px = x + (size_t)bb * TOTAL_DIM + SEGOFF + (size_t)jj * LVALID + xf4 * 4;
    }

    float acc[2][8][4];
#pragma unroll
    for (int mt = 0; mt < 2; mt++)
#pragma unroll
        for (int t = 0; t < 8; t++)
#pragma unroll
            for (int c = 0; c < 4; c++) acc[mt][t][c] = 0.f;

    // ---- prologue: B chunk0 -> stage0, x chunk0 -> regs ----
    const __nv_bfloat16* bh16 = (const __nv_bfloat16*)wbh;
    const __nv_bfloat16* bl16 = (const __nv_bfloat16*)wbl;
#pragma unroll
    for (int i = 0; i < 4; i++) {
        int fi = tid + i * THREADS;          // 0..2047
        int kr = fi >> 6, cc = fi & 63;
        cp16(sb + OFF_B + kr * B_ROWB + cc * 16, bh16 + (size_t)kr * 512 + cc * 8);
        cp16(sb + OFF_B + B_PLANE + kr * B_ROWB + cc * 16, bl16 + (size_t)kr * 512 + cc * 8);
    }
    asm volatile("cp.async.commit_group;" ::: "memory");

    float4 xv;
    {
        int k0 = xf4 * 4;
        xv = (k0 + 4 <= LVALID) ? *(const float4*)(px) : make_float4(0.f, 0.f, 0.f, 0.f);
    }

    for (int c = 0; c < NCHUNK; c++) {
        const int s = c & 1;
        const uint32_t aH = sb + OFF_A + s * A_STAGE;
        const uint32_t aL = aH + A_PLANE;

        // STS A(c): split to bf16 hi/lo
        {
            uint16_t h0, h1, h2, h3, l0, l1, l2, l3;
            bf16_split(xv.x, h0, l0); bf16_split(xv.y, h1, l1);
            bf16_split(xv.z, h2, l2); bf16_split(xv.w, h3, l3);
            uint2 ph = make_uint2((uint32_t)h0 | ((uint32_t)h1 << 16),
                                  (uint32_t)h2 | ((uint32_t)h3 << 16));
            uint2 pl = make_uint2((uint32_t)l0 | ((uint32_t)l1 << 16),
                                  (uint32_t)l2 | ((uint32_t)l3 << 16));
            uint32_t off = (uint32_t)(xrow * A_ROWB + xf4 * 8);
            *(uint2*)(smem + OFF_A + s * A_STAGE + off) = ph;
            *(uint2*)(smem + OFF_A + s * A_STAGE + A_PLANE + off) = pl;
        }

        asm volatile("cp.async.wait_group 0;" ::: "memory");
        __syncthreads();

        // issue next chunk's loads (B -> other stage; x -> regs)
        if (c + 1 < NCHUNK) {
            const uint32_t bDst = sb + OFF_B + (s ^ 1) * B_STAGE;
            const size_t kbase = (size_t)(c + 1) * 32 * 512;
#pragma unroll
            for (int i = 0; i < 4; i++) {
                int fi = tid + i * THREADS;
                int kr = fi >> 6, cc = fi & 63;
                cp16(bDst + kr * B_ROWB + cc * 16, bh16 + kbase + (size_t)kr * 512 + cc * 8);
                cp16(bDst + B_PLANE + kr * B_ROWB + cc * 16, bl16 + kbase + (size_t)kr * 512 + cc * 8);
            }
            asm volatile("cp.async.commit_group;" ::: "memory");
            int k0 = (c + 1) * 32 + xf4 * 4;
            xv = (k0 + 4 <= LVALID) ? *(const float4*)(px + (c + 1) * 32)
                                    : make_float4(0.f, 0.f, 0.f, 0.f);
        }

        // ---- compute stage s ----
        const uint32_t bH = sb + OFF_B + s * B_STAGE;
        const uint32_t bL = bH + B_PLANE;
#pragma unroll
        for (int ks = 0; ks < 2; ks++) {
            const uint32_t arow = (uint32_t)(wm * 32 + (lane & 15));
            const uint32_t acol = (uint32_t)(((lane >> 4) << 3) + ks * 16);
            uint32_t ah[2][4], al[2][4];
#pragma unroll
            for (int mt = 0; mt < 2; mt++) {
                uint32_t aoff = (arow + mt * 16) * A_ROWB + acol * 2;
                LDSM_X4(ah[mt][0], ah[mt][1], ah[mt][2], ah[mt][3], aH + aoff);
                LDSM_X4(al[mt][0], al[mt][1], al[mt][2], al[mt][3], aL + aoff);
            }
            const uint32_t brow = (uint32_t)(ks * 16 + (lane & 15));
#pragma unroll
            for (int g = 0; g < 4; g++) {
                const uint32_t bcol = (uint32_t)(wn * 64 + g * 16 + ((lane >> 4) << 3));
                const uint32_t boff = brow * B_ROWB + bcol * 2;
                uint32_t b0, b1, b2, b3, c0, c1, c2, c3;
                LDSM_X4T(b0, b1, b2, b3, bH + boff);
                LDSM_X4T(c0, c1, c2, c3, bL + boff);
#pragma unroll
                for (int mt = 0; mt < 2; mt++) {
                    MMA16816(acc[mt][2 * g],     ah[mt][0], ah[mt][1], ah[mt][2], ah[mt][3], b0, b1);
                    MMA16816(acc[mt][2 * g + 1], ah[mt][0], ah[mt][1], ah[mt][2], ah[mt][3], b2, b3);
                    MMA16816(acc[mt][2 * g],     al[mt][0], al[mt][1], al[mt][2], al[mt][3], b0, b1);
                    MMA16816(acc[mt][2 * g + 1], al[mt][0], al[mt][1], al[mt][2], al[mt][3], b2, b3);
                    MMA16816(acc[mt][2 * g],     ah[mt][0], ah[mt][1], ah[mt][2], ah[mt][3], c0, c1);
                    MMA16816(acc[mt][2 * g + 1], ah[mt][0], ah[mt][1], ah[mt][2], ah[mt][3], c2, c3);
                }
            }
        }
    }

    // ================= epilogue: bias + ReLU + LN =================
    float* ssum = (float*)(smem + OFF_SSUM);
    float* sssq = (float*)(smem + OFF_SSSQ);
    float* rst  = (float*)(smem + OFF_RST);

#pragma unroll
    for (int mt = 0; mt < 2; mt++) {
        float sum0 = 0.f, ssq0 = 0.f, sum1 = 0.f, ssq1 = 0.f;
#pragma unroll
        for (int t = 0; t < 8; t++) {
            int cb = wn * 64 + t * 8 + (lane & 3) * 2;
            float b0v = bias_s[cb], b1v = bias_s[cb + 1];
            float h;
            h = fmaxf(acc[mt][t][0] + b0v, 0.f); acc[mt][t][0] = h; sum0 += h; ssq0 += h * h;
            h = fmaxf(acc[mt][t][1] + b1v, 0.f); acc[mt][t][1] = h; sum0 += h; ssq0 += h * h;
            h = fmaxf(acc[mt][t][2] + b0v, 0.f); acc[mt][t][2] = h; sum1 += h; ssq1 += h * h;
            h = fmaxf(acc[mt][t][3] + b1v, 0.f); acc[mt][t][3] = h; sum1 += h; ssq1 += h * h;
        }
#pragma unroll
        for (int o = 1; o <= 2; o <<= 1) {
            sum0 += __shfl_xor_sync(0xffffffffu, sum0, o);
            ssq0 += __shfl_xor_sync(0xffffffffu, ssq0, o);
            sum1 += __shfl_xor_sync(0xffffffffu, sum1, o);
            ssq1 += __shfl_xor_sync(0xffffffffu, ssq1, o);
        }
        if ((lane & 3) == 0) {
            int r0 = wm * 32 + mt * 16 + (lane >> 2);
            ssum[r0 * 8 + wn] = sum0;       sssq[r0 * 8 + wn] = ssq0;
            ssum[(r0 + 8) * 8 + wn] = sum1; sssq[(r0 + 8) * 8 + wn] = ssq1;
        }
    }
    __syncthreads();
    if (tid < 64) {
        float s = 0.f, q = 0.f;
#pragma unroll
        for (int i = 0; i < 8; i++) { s += ssum[tid * 8 + i]; q += sssq[tid * 8 + i]; }
        float mean = s * (1.f / 512.f);
        float var  = q * (1.f / 512.f) - mean * mean;
        rst[tid * 2] = mean;
        rst[tid * 2 + 1] = rsqrtf(var + 1e-5f);
    }
    __syncthreads();

#pragma unroll
    for (int mt = 0; mt < 2; mt++) {
        int r0 = wm * 32 + mt * 16 + (lane >> 2);
        float m0 = rst[r0 * 2], rs0 = rst[r0 * 2 + 1];
        float m1 = rst[(r0 + 8) * 2], rs1 = rst[(r0 + 8) * 2 + 1];
        int gr0 = row0 + r0, gr1 = gr0 + 8;
        int b0i = gr0 / KSPLIT, j0 = gr0 - b0i * KSPLIT;
        int b1i = gr1 / KSPLIT, j1 = gr1 - b1i * KSPLIT;
        float* o0 = out + ((size_t)b0i * NQ + QOFF + j0) * 512;
        float* o1 = out + ((size_t)b1i * NQ + QOFF + j1) * 512;
#pragma unroll
        for (int t = 0; t < 8; t++) {
            int cb = wn * 64 + t * 8 + (lane & 3) * 2;
            float g0 = gam_s[cb], g1 = gam_s[cb + 1];
            float e0 = bet_s[cb], e1 = bet_s[cb + 1];
            float2 v0 = make_float2((acc[mt][t][0] - m0) * rs0 * g0 + e0,
                                    (acc[mt][t][1] - m0) * rs0 * g1 + e1);
            float2 v1 = make_float2((acc[mt][t][2] - m1) * rs1 * g0 + e0,
                                    (acc[mt][t][3] - m1) * rs1 * g1 + e1);
            *(float2*)(o0 + cb) = v0;
            *(float2*)(o1 + cb) = v1;
        }
    }
}

__global__ void __launch_bounds__(THREADS, 1)
fused_kernel(const float* __restrict__ x,
             const float* b0, const float* g0, const float* be0,
             const float* b1, const float* g1, const float* be1,
             const float* b2, const float* g2, const float* be2,
             float* __restrict__ out) {
    const int blk = blockIdx.x;
    if (blk < 32)         run_split<1,  400, 13, 0,     0 >(x, b0, g0, be0, out, g_bh0, g_bl0, blk);
    else if (blk < 1952)  run_split<60, 256, 8,  400,   1 >(x, b1, g1, be1, out, g_bh1, g_bl1, blk - 32);
    else                  run_split<36, 256, 8,  15760, 61>(x, b2, g2, be2, out, g_bh2, g_bl2, blk - 1952);
}

// ================= weight prep: W f32 -> bf16 hi/lo planes =================
__device__ __forceinline__ void prep_one(const float* __restrict__ W, uint4* bh, uint4* bl,
                                         int Lvalid, int idx) {
    int k = idx >> 9, n = idx & 511;
    float v = (k < Lvalid) ? W[(size_t)k * 512 + n] : 0.f;
    uint16_t h, l;
    bf16_split(v, h, l);
    ((uint16_t*)bh)[idx] = h;
    ((uint16_t*)bl)[idx] = l;
}

__global__ void prep_kernel(const float* __restrict__ W0, const float* __restrict__ W1,
                            const float* __restrict__ W2) {
    const int idx = blockIdx.x * blockDim.x + threadIdx.x;
    const int T0 = 416 * 512, T1 = 256 * 512, T2 = 256 * 512;
    if (idx < T0)                prep_one(W0, g_bh0, g_bl0, 400, idx);
    else if (idx < T0 + T1)      prep_one(W1, g_bh1, g_bl1, 256, idx - T0);
    else if (idx < T0 + T1 + T2) prep_one(W2, g_bh2, g_bl2, 256, idx - T0 - T1);
}

// ================= launch =================
extern "C" void kernel_launch(void* const* d_in, const int* in_sizes, int n_in,
                              void* d_out, int out_size) {
    (void)in_sizes; (void)n_in; (void)out_size;
    const float* x = (const float*)d_in[0];
    float* out = (float*)d_out;

    cudaFuncSetAttribute(fused_kernel, cudaFuncAttributeMaxDynamicSharedMemorySize, SMEM_TOTAL);

    const int prep_total = (416 + 256 + 256) * 512;
    prep_kernel<<<(prep_total + 255) / 256, 256>>>(
        (const float*)d_in[1], (const float*)d_in[5], (const float*)d_in[9]);

    fused_kernel<<<3104, THREADS, SMEM_TOTAL>>>(
        x,
        (const float*)d_in[2],  (const float*)d_in[3],  (const float*)d_in[4],
        (const float*)d_in[6],  (const float*)d_in[7],  (const float*)d_in[8],
        (const float*)d_in[10], (const float*)d_in[11], (const float*)d_in[12],
        out);
}